// round 6
// baseline (speedup 1.0000x reference)
#include <cuda_runtime.h>

typedef unsigned long long u64;

#define NQ 22
#define DIM (1 << NQ)
#define NL 4

// State stored at PAIR granularity: uint4 = (re0, re1, im0, im1) for amps (2p, 2p+1).
__device__ __align__(16) uint4 g_state[DIM / 2];
__device__ float  g_norm_partial[1024];
__device__ float  g_inv_norm;
__device__ float2 g_Ug[NL][NQ][4];    // fused RZ*RY*RX (float2 form, for scalar intra gate)
__device__ u64    g_Up[NL][NQ][12];   // packed broadcast constants: r,i,-i per matrix entry
__device__ float  g_zpart[256][22];

// Bank swizzle over pair-index q (8192 pairs per tile): fold bits 3..5 into 0..2.
__device__ __forceinline__ int sig(int q) { return q ^ ((q >> 3) & 7); }

__device__ __forceinline__ u64 pk2(float x) {
    unsigned b = __float_as_uint(x);
    return ((u64)b << 32) | (u64)b;
}
__device__ __forceinline__ float ulo(u64 v) { return __uint_as_float((unsigned)v); }
__device__ __forceinline__ float uhi(u64 v) { return __uint_as_float((unsigned)(v >> 32)); }
__device__ __forceinline__ u64 f2u(float lo, float hi) {
    return ((u64)__float_as_uint(hi) << 32) | (u64)__float_as_uint(lo);
}

#define FMA2(d, a, b, c) asm("fma.rn.f32x2 %0, %1, %2, %3;" : "=l"(d) : "l"(a), "l"(b), "l"(c))
#define MUL2(d, a, b)    asm("mul.rn.f32x2 %0, %1, %2;"     : "=l"(d) : "l"(a), "l"(b))

struct G12 { u64 r00, i00, n00, r01, i01, n01, r10, i10, n10, r11, i11, n11; };

__device__ __forceinline__ G12 load_gate(int l, int q) {
    const u64* p = g_Up[l][q];
    G12 g;
    g.r00 = p[0];  g.i00 = p[1];  g.n00 = p[2];
    g.r01 = p[3];  g.i01 = p[4];  g.n01 = p[5];
    g.r10 = p[6];  g.i10 = p[7];  g.n10 = p[8];
    g.r11 = p[9];  g.i11 = p[10]; g.n11 = p[11];
    return g;
}

// Packed complex 2x2 gate between packs (a0) and (a1); both packed lanes independent.
__device__ __forceinline__ void pgate(u64& a0r, u64& a0i, u64& a1r, u64& a1i, const G12& g) {
    u64 b0r, b0i, b1r, b1i;
    MUL2(b0r, g.r00, a0r); FMA2(b0r, g.n00, a0i, b0r); FMA2(b0r, g.r01, a1r, b0r); FMA2(b0r, g.n01, a1i, b0r);
    MUL2(b0i, g.r00, a0i); FMA2(b0i, g.i00, a0r, b0i); FMA2(b0i, g.r01, a1i, b0i); FMA2(b0i, g.i01, a1r, b0i);
    MUL2(b1r, g.r10, a0r); FMA2(b1r, g.n10, a0i, b1r); FMA2(b1r, g.r11, a1r, b1r); FMA2(b1r, g.n11, a1i, b1r);
    MUL2(b1i, g.r10, a0i); FMA2(b1i, g.i10, a0r, b1i); FMA2(b1i, g.r11, a1i, b1i); FMA2(b1i, g.i11, a1r, b1i);
    a0r = b0r; a0i = b0i; a1r = b1r; a1i = b1i;
}

// One radix-8 pass over pair-bits pb, pb+1, pb+2 (gates q0, q1, q2).
// If intra: first apply gate qi between the two packed lanes (scalar).
__device__ __forceinline__ void do_pass(uint4* sh, int t, int pb,
                                        int q0, int q1, int q2, int l,
                                        bool intra, int qi) {
    const int low = t & ((1 << pb) - 1);
    const int hi  = t >> pb;
    const int qbase = (hi << (pb + 3)) | low;
    u64 re2[8], im2[8];
#pragma unroll
    for (int s = 0; s < 8; s++) {
        uint4 v = sh[sig(qbase | (s << pb))];
        re2[s] = ((u64)v.y << 32) | v.x;
        im2[s] = ((u64)v.w << 32) | v.z;
    }
    if (intra) {
        float2 u00 = g_Ug[l][qi][0], u01 = g_Ug[l][qi][1];
        float2 u10 = g_Ug[l][qi][2], u11 = g_Ug[l][qi][3];
#pragma unroll
        for (int s = 0; s < 8; s++) {
            float a0r = ulo(re2[s]), a1r = uhi(re2[s]);
            float a0i = ulo(im2[s]), a1i = uhi(im2[s]);
            float b0r = u00.x*a0r - u00.y*a0i + u01.x*a1r - u01.y*a1i;
            float b0i = u00.x*a0i + u00.y*a0r + u01.x*a1i + u01.y*a1r;
            float b1r = u10.x*a0r - u10.y*a0i + u11.x*a1r - u11.y*a1i;
            float b1i = u10.x*a0i + u10.y*a0r + u11.x*a1i + u11.y*a1r;
            re2[s] = f2u(b0r, b1r);
            im2[s] = f2u(b0i, b1i);
        }
    }
    {
        G12 g = load_gate(l, q0);
#pragma unroll
        for (int s = 0; s < 8; s++) if (!(s & 1))
            pgate(re2[s], im2[s], re2[s | 1], im2[s | 1], g);
    }
    {
        G12 g = load_gate(l, q1);
#pragma unroll
        for (int s = 0; s < 8; s++) if (!(s & 2))
            pgate(re2[s], im2[s], re2[s | 2], im2[s | 2], g);
    }
    {
        G12 g = load_gate(l, q2);
#pragma unroll
        for (int s = 0; s < 8; s++) if (!(s & 4))
            pgate(re2[s], im2[s], re2[s | 4], im2[s | 4], g);
    }
#pragma unroll
    for (int s = 0; s < 8; s++) {
        uint4 v;
        v.x = (unsigned)re2[s]; v.y = (unsigned)(re2[s] >> 32);
        v.z = (unsigned)im2[s]; v.w = (unsigned)(im2[s] >> 32);
        sh[sig(qbase | (s << pb))] = v;
    }
}

// ---------------------------------------------------------------------------
// Norm reduction (reads inputs only)
// ---------------------------------------------------------------------------
__global__ void norm_part(const float* __restrict__ re, const float* __restrict__ im) {
    int tid = threadIdx.x;
    int base = blockIdx.x * 4096;
    float acc = 0.f;
#pragma unroll
    for (int k = 0; k < 16; k++) {
        int idx = base + k * 256 + tid;
        float r = re[idx], m = im[idx];
        acc = fmaf(r, r, acc);
        acc = fmaf(m, m, acc);
    }
    for (int off = 16; off; off >>= 1) acc += __shfl_xor_sync(0xffffffffu, acc, off);
    __shared__ float ws[8];
    int lane = tid & 31, wp = tid >> 5;
    if (lane == 0) ws[wp] = acc;
    __syncthreads();
    if (wp == 0) {
        float v = (lane < 8) ? ws[lane] : 0.f;
        for (int off = 4; off; off >>= 1) v += __shfl_xor_sync(0xffffffffu, v, off);
        if (lane == 0) g_norm_partial[blockIdx.x] = v;
    }
}

__global__ void norm_finalize() {
    int tid = threadIdx.x;
    float v = g_norm_partial[tid];
    for (int off = 16; off; off >>= 1) v += __shfl_xor_sync(0xffffffffu, v, off);
    __shared__ float ws[32];
    int lane = tid & 31, wp = tid >> 5;
    if (lane == 0) ws[wp] = v;
    __syncthreads();
    if (wp == 0) {
        float s = ws[lane];
        for (int off = 16; off; off >>= 1) s += __shfl_xor_sync(0xffffffffu, s, off);
        if (lane == 0) g_inv_norm = rsqrtf(s);
    }
}

// ---------------------------------------------------------------------------
// Fused single-qubit unitaries  U = RZ * RY * RX  (float2 table + packed table)
// ---------------------------------------------------------------------------
__device__ __forceinline__ float2 cmulf(float2 a, float2 b) {
    return make_float2(a.x * b.x - a.y * b.y, a.x * b.y + a.y * b.x);
}

__global__ void make_gates(const float* __restrict__ params) {
    int t = threadIdx.x;
    if (t >= NL * NQ) return;
    int l = t / NQ, q = t % NQ;
    const float* p = params + (l * NQ + q) * 3;
    float tx = 0.5f * p[0], ty = 0.5f * p[1], tz = 0.5f * p[2];
    float cx = cosf(tx), sx = sinf(tx);
    float cy = cosf(ty), sy = sinf(ty);
    float cz = cosf(tz), sz = sinf(tz);
    float2 m00 = make_float2( cy * cx,  sy * sx);
    float2 m01 = make_float2(-sy * cx, -cy * sx);
    float2 m10 = make_float2( sy * cx, -cy * sx);
    float2 m11 = make_float2( cy * cx, -sy * sx);
    float2 e0 = make_float2(cz, -sz);
    float2 e1 = make_float2(cz,  sz);
    float2 u00 = cmulf(e0, m00), u01 = cmulf(e0, m01);
    float2 u10 = cmulf(e1, m10), u11 = cmulf(e1, m11);
    g_Ug[l][q][0] = u00; g_Ug[l][q][1] = u01;
    g_Ug[l][q][2] = u10; g_Ug[l][q][3] = u11;
    u64* up = g_Up[l][q];
    up[0] = pk2(u00.x); up[1]  = pk2(u00.y); up[2]  = pk2(-u00.y);
    up[3] = pk2(u01.x); up[4]  = pk2(u01.y); up[5]  = pk2(-u01.y);
    up[6] = pk2(u10.x); up[7]  = pk2(u10.y); up[8]  = pk2(-u10.y);
    up[9] = pk2(u11.x); up[10] = pk2(u11.y); up[11] = pk2(-u11.y);
}

// ---------------------------------------------------------------------------
// Kernel A: tile bits {0..4} U {13..21}. Pair index q: bits 0..3 = amp bits 1..4,
// bits 4..12 = amp bits 13..21. Global pair addr gp = (q>>4)<<12 | blk<<4 | (q&15).
// Gates qubits 0..8 on pair bits 4..12 (pair-bit k -> qubit 12-k).
// Store CNOTs q=0..7: pq = q ^ ((q>>1)&0xFF0).
// ---------------------------------------------------------------------------
__global__ void __launch_bounds__(1024, 1)
layerA_kernel(int layer, const float* __restrict__ sre, const float* __restrict__ sim, int first) {
    extern __shared__ uint4 sh[];
    const int t = threadIdx.x;
    const int blk = blockIdx.x;

    if (first) {
        float s = g_inv_norm;
#pragma unroll
        for (int u = 0; u < 8; u++) {
            int q = u * 1024 + t;
            int j = (((q >> 4) << 12) | (blk << 4) | (q & 15)) << 1;
            float2 r2 = *(const float2*)&sre[j];
            float2 i2 = *(const float2*)&sim[j];
            uint4 v;
            v.x = __float_as_uint(r2.x * s); v.y = __float_as_uint(r2.y * s);
            v.z = __float_as_uint(i2.x * s); v.w = __float_as_uint(i2.y * s);
            sh[sig(q)] = v;
        }
    } else {
#pragma unroll
        for (int u = 0; u < 8; u++) {
            int q = u * 1024 + t;
            int gp = ((q >> 4) << 12) | (blk << 4) | (q & 15);
            sh[sig(q)] = g_state[gp];
        }
    }
    __syncthreads();

    do_pass(sh, t, 4,  8, 7, 6, layer, false, 0); __syncthreads();
    do_pass(sh, t, 7,  5, 4, 3, layer, false, 0); __syncthreads();
    do_pass(sh, t, 10, 2, 1, 0, layer, false, 0); __syncthreads();

#pragma unroll
    for (int u = 0; u < 8; u++) {
        int q = u * 1024 + t;
        int gp = ((q >> 4) << 12) | (blk << 4) | (q & 15);
        int pq = q ^ ((q >> 1) & 0xFF0);
        g_state[gp] = sh[sig(pq)];
    }
}

// ---------------------------------------------------------------------------
// Kernel B: contiguous tile, pair bits 0..12 (= amp bits 1..13), block = amp
// bits 14..21. Gates qubits 9..21 (pair-bit k -> qubit 20-k; in-pair -> 21).
// Store CNOTs q=8..20: pq = q ^ ((q>>1)&0xFFF); halves swapped iff q odd.
// ---------------------------------------------------------------------------
__global__ void __launch_bounds__(1024, 1)
layerB_kernel(int layer) {
    extern __shared__ uint4 sh[];
    const int t = threadIdx.x;
    const int base = blockIdx.x << 13;  // pair base

#pragma unroll
    for (int u = 0; u < 8; u++) {
        int q = u * 1024 + t;
        sh[sig(q)] = g_state[base + q];
    }
    __syncthreads();

    do_pass(sh, t, 0, 20, 19, 18, layer, true, 21); __syncthreads();
    do_pass(sh, t, 3, 17, 16, 15, layer, false, 0); __syncthreads();
    do_pass(sh, t, 6, 14, 13, 12, layer, false, 0); __syncthreads();
    do_pass(sh, t, 9, 11, 10,  9, layer, false, 0); __syncthreads();

    const bool swp = (t & 1) != 0;
#pragma unroll
    for (int u = 0; u < 8; u++) {
        int q = u * 1024 + t;
        int pq = q ^ ((q >> 1) & 0xFFF);
        uint4 v = sh[sig(pq)];
        if (swp) v = make_uint4(v.y, v.x, v.w, v.z);
        g_state[base + q] = v;
    }
}

// ---------------------------------------------------------------------------
// Z expectation values over pair layout. Pair p: amps 2p (lanes .x/.z) and
// 2p+1 (.y/.w). Amp bits: 0 = in-pair, 1..10 = tid, 11..13 = iter, 14..21 = blk.
// ---------------------------------------------------------------------------
__global__ void expval_kernel() {
    __shared__ float wsum[15][33];
    int tid = threadIdx.x, blk = blockIdx.x;
    int lane = tid & 31, wp = tid >> 5;
    float T = 0.f, D = 0.f, U0 = 0.f, U1 = 0.f, U2 = 0.f;
    int base = blk << 13;
#pragma unroll
    for (int i = 0; i < 8; i++) {
        uint4 v = g_state[base + (i << 10) + tid];
        float r0 = __uint_as_float(v.x), r1 = __uint_as_float(v.y);
        float m0 = __uint_as_float(v.z), m1 = __uint_as_float(v.w);
        float p0 = fmaf(r0, r0, m0 * m0);
        float p1 = fmaf(r1, r1, m1 * m1);
        float p = p0 + p1;
        T += p;
        D += p0 - p1;
        if (i & 1) U0 += p;
        if (i & 2) U1 += p;
        if (i & 4) U2 += p;
    }
    float z[15];
    z[0] = D;
#pragma unroll
    for (int b = 0; b < 10; b++) z[b + 1] = ((tid >> b) & 1) ? -T : T;
    z[11] = T - 2.f * U0;
    z[12] = T - 2.f * U1;
    z[13] = T - 2.f * U2;
    z[14] = T;
#pragma unroll
    for (int b = 0; b < 15; b++) {
        float v = z[b];
        for (int off = 16; off; off >>= 1) v += __shfl_xor_sync(0xffffffffu, v, off);
        if (lane == 0) wsum[b][wp] = v;
    }
    __syncthreads();
    if (tid < 15) {
        float s = 0.f;
        for (int w = 0; w < 32; w++) s += wsum[tid][w];
        wsum[tid][32] = s;
    }
    __syncthreads();
    if (tid < 22) {
        float v;
        if (tid < 14) v = wsum[tid][32];
        else          v = (((blk >> (tid - 14)) & 1) ? -wsum[14][32] : wsum[14][32]);
        g_zpart[blk][tid] = v;
    }
}

__global__ void final_reduce(float* __restrict__ out) {
    int q = threadIdx.x;
    if (q >= 22) return;
    int b = 21 - q;   // qubit q <-> amp bit 21-q
    float s = 0.f;
    for (int i = 0; i < 256; i++) s += g_zpart[i][b];
    out[q] = s;
}

// ---------------------------------------------------------------------------
extern "C" void kernel_launch(void* const* d_in, const int* in_sizes, int n_in,
                              void* d_out, int out_size) {
    const float* params = (const float*)d_in[0];
    const float* re     = (const float*)d_in[1];
    const float* im     = (const float*)d_in[2];
    float* out = (float*)d_out;

    cudaFuncSetAttribute(layerA_kernel, cudaFuncAttributeMaxDynamicSharedMemorySize, 131072);
    cudaFuncSetAttribute(layerB_kernel, cudaFuncAttributeMaxDynamicSharedMemorySize, 131072);

    norm_part<<<1024, 256>>>(re, im);
    norm_finalize<<<1, 1024>>>();
    make_gates<<<1, 128>>>(params);
    for (int l = 0; l < NL; l++) {
        layerA_kernel<<<256, 1024, 131072>>>(l, re, im, l == 0 ? 1 : 0);
        layerB_kernel<<<256, 1024, 131072>>>(l);
    }
    expval_kernel<<<256, 1024>>>();
    final_reduce<<<1, 32>>>(out);
}

// round 7
// speedup vs baseline: 1.2867x; 1.2867x over previous
#include <cuda_runtime.h>

#define NQ 22
#define DIM (1 << NQ)
#define NL 4

// State at PAIR granularity: float4 = (re0, im0, re1, im1) for amps (2p, 2p+1).
__device__ __align__(16) float4 g_state[DIM / 2];
__device__ float  g_norm_partial[1024];
__device__ float  g_inv_norm;
__device__ float2 g_Ug[NL][NQ][4];   // fused RZ*RY*RX per (layer,qubit)
__device__ float  g_zpart[256][22];

// Bank swizzle over tile pair-index q: fold bits 3..5 into 0..2.
__device__ __forceinline__ int sig(int q) { return q ^ ((q >> 3) & 7); }

struct C2 { float2 u00, u01, u10, u11; };

__device__ __forceinline__ C2 getU(int l, int q) {
    C2 c;
    c.u00 = g_Ug[l][q][0]; c.u01 = g_Ug[l][q][1];
    c.u10 = g_Ug[l][q][2]; c.u11 = g_Ug[l][q][3];
    return c;
}

// Complex 2x2 gate: x' = u00*x + u01*y ; y' = u10*x + u11*y
__device__ __forceinline__ void cgate(float2& x, float2& y, const C2& U) {
    float nxr = U.u00.x*x.x - U.u00.y*x.y + U.u01.x*y.x - U.u01.y*y.y;
    float nxi = U.u00.x*x.y + U.u00.y*x.x + U.u01.x*y.y + U.u01.y*y.x;
    float nyr = U.u10.x*x.x - U.u10.y*x.y + U.u11.x*y.x - U.u11.y*y.y;
    float nyi = U.u10.x*x.y + U.u10.y*x.x + U.u11.x*y.y + U.u11.y*y.x;
    x = make_float2(nxr, nxi);
    y = make_float2(nyr, nyi);
}

// One radix-8 pass over pair-bits pb, pb+1, pb+2 (gates q0, q1, q2).
// If intra, first applies gate qi on the in-pair bit. 512 threads x 8 pairs = 4096-pair tile.
__device__ __forceinline__ void do_pass(float4* sh4, int t, int pb,
                                        int q0, int q1, int q2, int l,
                                        bool intra, int qi) {
    const int low = t & ((1 << pb) - 1);
    const int hi  = t >> pb;
    const int qbase = (hi << (pb + 3)) | low;
    float2 a[16];
#pragma unroll
    for (int s = 0; s < 8; s++) {
        float4 v = sh4[sig(qbase | (s << pb))];
        a[2*s]   = make_float2(v.x, v.y);
        a[2*s+1] = make_float2(v.z, v.w);
    }
    if (intra) {
        C2 U = getU(l, qi);
#pragma unroll
        for (int s = 0; s < 8; s++) cgate(a[2*s], a[2*s+1], U);
    }
    {
        C2 U = getU(l, q0);
#pragma unroll
        for (int s = 0; s < 8; s++) if (!(s & 1)) {
            cgate(a[2*s],   a[2*(s|1)],   U);
            cgate(a[2*s+1], a[2*(s|1)+1], U);
        }
    }
    {
        C2 U = getU(l, q1);
#pragma unroll
        for (int s = 0; s < 8; s++) if (!(s & 2)) {
            cgate(a[2*s],   a[2*(s|2)],   U);
            cgate(a[2*s+1], a[2*(s|2)+1], U);
        }
    }
    {
        C2 U = getU(l, q2);
#pragma unroll
        for (int s = 0; s < 8; s++) if (!(s & 4)) {
            cgate(a[2*s],   a[2*(s|4)],   U);
            cgate(a[2*s+1], a[2*(s|4)+1], U);
        }
    }
#pragma unroll
    for (int s = 0; s < 8; s++) {
        sh4[sig(qbase | (s << pb))] =
            make_float4(a[2*s].x, a[2*s].y, a[2*s+1].x, a[2*s+1].y);
    }
}

// ---------------------------------------------------------------------------
// Norm reduction (reads inputs only)
// ---------------------------------------------------------------------------
__global__ void norm_part(const float* __restrict__ re, const float* __restrict__ im) {
    int tid = threadIdx.x;
    int base = blockIdx.x * 4096;
    float acc = 0.f;
#pragma unroll
    for (int k = 0; k < 16; k++) {
        int idx = base + k * 256 + tid;
        float r = re[idx], m = im[idx];
        acc = fmaf(r, r, acc);
        acc = fmaf(m, m, acc);
    }
    for (int off = 16; off; off >>= 1) acc += __shfl_xor_sync(0xffffffffu, acc, off);
    __shared__ float ws[8];
    int lane = tid & 31, wp = tid >> 5;
    if (lane == 0) ws[wp] = acc;
    __syncthreads();
    if (wp == 0) {
        float v = (lane < 8) ? ws[lane] : 0.f;
        for (int off = 4; off; off >>= 1) v += __shfl_xor_sync(0xffffffffu, v, off);
        if (lane == 0) g_norm_partial[blockIdx.x] = v;
    }
}

__global__ void norm_finalize() {
    int tid = threadIdx.x;
    float v = g_norm_partial[tid];
    for (int off = 16; off; off >>= 1) v += __shfl_xor_sync(0xffffffffu, v, off);
    __shared__ float ws[32];
    int lane = tid & 31, wp = tid >> 5;
    if (lane == 0) ws[wp] = v;
    __syncthreads();
    if (wp == 0) {
        float s = ws[lane];
        for (int off = 16; off; off >>= 1) s += __shfl_xor_sync(0xffffffffu, s, off);
        if (lane == 0) g_inv_norm = rsqrtf(s);
    }
}

// ---------------------------------------------------------------------------
// Fused single-qubit unitaries  U = RZ * RY * RX
// ---------------------------------------------------------------------------
__device__ __forceinline__ float2 cmulf(float2 a, float2 b) {
    return make_float2(a.x * b.x - a.y * b.y, a.x * b.y + a.y * b.x);
}

__global__ void make_gates(const float* __restrict__ params) {
    int t = threadIdx.x;
    if (t >= NL * NQ) return;
    int l = t / NQ, q = t % NQ;
    const float* p = params + (l * NQ + q) * 3;
    float tx = 0.5f * p[0], ty = 0.5f * p[1], tz = 0.5f * p[2];
    float cx = cosf(tx), sx = sinf(tx);
    float cy = cosf(ty), sy = sinf(ty);
    float cz = cosf(tz), sz = sinf(tz);
    float2 m00 = make_float2( cy * cx,  sy * sx);
    float2 m01 = make_float2(-sy * cx, -cy * sx);
    float2 m10 = make_float2( sy * cx, -cy * sx);
    float2 m11 = make_float2( cy * cx, -sy * sx);
    float2 e0 = make_float2(cz, -sz);
    float2 e1 = make_float2(cz,  sz);
    g_Ug[l][q][0] = cmulf(e0, m00);
    g_Ug[l][q][1] = cmulf(e0, m01);
    g_Ug[l][q][2] = cmulf(e1, m10);
    g_Ug[l][q][3] = cmulf(e1, m11);
}

// ---------------------------------------------------------------------------
// Kernel A: 4096-pair tile over global-pair bits {0..2} U {12..20}
//   (tile q bits 0..2 = gp bits 0..2 = amp bits 1..3; q bits 3..11 = gp bits
//    12..20 = amp bits 13..21).  gp = ((q>>3)<<12) | (blk<<3) | (q&7).
// Gates qubits 0..8: q bit k -> qubit 11-k. Passes pb=3 (8,7,6), 6 (5,4,3), 9 (2,1,0).
// Store CNOTs q=0..7 (gather): pq = q ^ ((q>>1)&0x7F8)  [q bits 3..10 ^= next bit].
// ---------------------------------------------------------------------------
__global__ void __launch_bounds__(512, 2)
layerA_kernel(int layer, const float* __restrict__ sre, const float* __restrict__ sim, int first) {
    extern __shared__ float4 sh4[];
    const int t = threadIdx.x;
    const int blk = blockIdx.x;   // gp bits 3..11 (9 bits)

    if (first) {
        float s = g_inv_norm;
#pragma unroll
        for (int u = 0; u < 8; u++) {
            int q = u * 512 + t;
            int gp = ((q >> 3) << 12) | (blk << 3) | (q & 7);
            int j = gp << 1;
            float2 r2 = *(const float2*)&sre[j];
            float2 i2 = *(const float2*)&sim[j];
            sh4[sig(q)] = make_float4(r2.x * s, i2.x * s, r2.y * s, i2.y * s);
        }
    } else {
#pragma unroll
        for (int u = 0; u < 8; u++) {
            int q = u * 512 + t;
            int gp = ((q >> 3) << 12) | (blk << 3) | (q & 7);
            sh4[sig(q)] = g_state[gp];
        }
    }
    __syncthreads();

    do_pass(sh4, t, 3, 8, 7, 6, layer, false, 0); __syncthreads();
    do_pass(sh4, t, 6, 5, 4, 3, layer, false, 0); __syncthreads();
    do_pass(sh4, t, 9, 2, 1, 0, layer, false, 0); __syncthreads();

#pragma unroll
    for (int u = 0; u < 8; u++) {
        int q = u * 512 + t;
        int gp = ((q >> 3) << 12) | (blk << 3) | (q & 7);
        int pq = q ^ ((q >> 1) & 0x7F8);
        g_state[gp] = sh4[sig(pq)];
    }
}

// ---------------------------------------------------------------------------
// Kernel B: contiguous 4096-pair tile (gp bits 0..11 = amp bits 1..12 + in-pair).
// Block = gp bits 12..20 (amp bits 13..21). Gates qubits 9..21:
//   in-pair -> qubit 21; q bit k -> qubit 20-k.
// Passes: pb=0 intra(21) + (20,19,18); pb=3 (17,16,15); pb=6 (14,13,12); pb=9 (11,10,9).
// Store CNOTs q=8..20 (gather): pq = q ^ ((q>>1)&0x7FF) ^ ((blk&1)<<11);
//   halves swapped iff q odd (out amp bit0 = bit0 ^ bit1).
// ---------------------------------------------------------------------------
__global__ void __launch_bounds__(512, 2)
layerB_kernel(int layer) {
    extern __shared__ float4 sh4[];
    const int t = threadIdx.x;
    const int blk = blockIdx.x;
    const int base = blk << 12;   // pair base

#pragma unroll
    for (int u = 0; u < 8; u++) {
        int q = u * 512 + t;
        sh4[sig(q)] = g_state[base + q];
    }
    __syncthreads();

    do_pass(sh4, t, 0, 20, 19, 18, layer, true, 21); __syncthreads();
    do_pass(sh4, t, 3, 17, 16, 15, layer, false, 0); __syncthreads();
    do_pass(sh4, t, 6, 14, 13, 12, layer, false, 0); __syncthreads();
    do_pass(sh4, t, 9, 11, 10,  9, layer, false, 0); __syncthreads();

    const bool swp = (t & 1) != 0;   // q&1 == t&1 since q = u*512 + t
    const int bx = (blk & 1) << 11;
#pragma unroll
    for (int u = 0; u < 8; u++) {
        int q = u * 512 + t;
        int pq = q ^ ((q >> 1) & 0x7FF) ^ bx;
        float4 v = sh4[sig(pq)];
        if (swp) v = make_float4(v.z, v.w, v.x, v.y);
        g_state[base + q] = v;
    }
}

// ---------------------------------------------------------------------------
// Z expectation values over pair layout. Pair bits: 0..9 = tid, 10..12 = iter,
// 13..20 = blk. Amp bits: 0 = in-pair, 1..10 = tid, 11..13 = iter, 14..21 = blk.
// ---------------------------------------------------------------------------
__global__ void expval_kernel() {
    __shared__ float wsum[15][33];
    int tid = threadIdx.x, blk = blockIdx.x;
    int lane = tid & 31, wp = tid >> 5;
    float T = 0.f, D = 0.f, U0 = 0.f, U1 = 0.f, U2 = 0.f;
    int base = blk << 13;
#pragma unroll
    for (int i = 0; i < 8; i++) {
        float4 v = g_state[base + (i << 10) + tid];
        float p0 = fmaf(v.x, v.x, v.y * v.y);
        float p1 = fmaf(v.z, v.z, v.w * v.w);
        float p = p0 + p1;
        T += p;
        D += p0 - p1;
        if (i & 1) U0 += p;
        if (i & 2) U1 += p;
        if (i & 4) U2 += p;
    }
    float z[15];
    z[0] = D;
#pragma unroll
    for (int b = 0; b < 10; b++) z[b + 1] = ((tid >> b) & 1) ? -T : T;
    z[11] = T - 2.f * U0;
    z[12] = T - 2.f * U1;
    z[13] = T - 2.f * U2;
    z[14] = T;
#pragma unroll
    for (int b = 0; b < 15; b++) {
        float v = z[b];
        for (int off = 16; off; off >>= 1) v += __shfl_xor_sync(0xffffffffu, v, off);
        if (lane == 0) wsum[b][wp] = v;
    }
    __syncthreads();
    if (tid < 15) {
        float s = 0.f;
        for (int w = 0; w < 32; w++) s += wsum[tid][w];
        wsum[tid][32] = s;
    }
    __syncthreads();
    if (tid < 22) {
        float v;
        if (tid < 14) v = wsum[tid][32];
        else          v = (((blk >> (tid - 14)) & 1) ? -wsum[14][32] : wsum[14][32]);
        g_zpart[blk][tid] = v;
    }
}

__global__ void final_reduce(float* __restrict__ out) {
    int q = threadIdx.x;
    if (q >= 22) return;
    int b = 21 - q;   // qubit q <-> amp bit 21-q
    float s = 0.f;
    for (int i = 0; i < 256; i++) s += g_zpart[i][b];
    out[q] = s;
}

// ---------------------------------------------------------------------------
extern "C" void kernel_launch(void* const* d_in, const int* in_sizes, int n_in,
                              void* d_out, int out_size) {
    const float* params = (const float*)d_in[0];
    const float* re     = (const float*)d_in[1];
    const float* im     = (const float*)d_in[2];
    float* out = (float*)d_out;

    cudaFuncSetAttribute(layerA_kernel, cudaFuncAttributeMaxDynamicSharedMemorySize, 65536);
    cudaFuncSetAttribute(layerB_kernel, cudaFuncAttributeMaxDynamicSharedMemorySize, 65536);

    norm_part<<<1024, 256>>>(re, im);
    norm_finalize<<<1, 1024>>>();
    make_gates<<<1, 128>>>(params);
    for (int l = 0; l < NL; l++) {
        layerA_kernel<<<512, 512, 65536>>>(l, re, im, l == 0 ? 1 : 0);
        layerB_kernel<<<512, 512, 65536>>>(l);
    }
    expval_kernel<<<256, 1024>>>();
    final_reduce<<<1, 32>>>(out);
}

// round 8
// speedup vs baseline: 1.3908x; 1.0809x over previous
#include <cuda_runtime.h>

#define NQ 22
#define DIM (1 << NQ)
#define NL 4

// State at PAIR granularity: float4 = (re0, im0, re1, im1) for amps (2p, 2p+1).
__device__ __align__(16) float4 g_state[DIM / 2];
__device__ float  g_norm_partial[1024];
__device__ float  g_inv_norm;
__device__ float2 g_Ug[NL][NQ][4];   // fused RZ*RY*RX per (layer,qubit)
__device__ float  g_zpart[256][22];

// Bank swizzle over tile pair-index q: fold bits 3..5 into 0..2.
__device__ __forceinline__ int sig(int q) { return q ^ ((q >> 3) & 7); }

// Suffix-parity over 12-bit value: bit b -> parity(y_b..y_11). (Inverse of the
// XOR-shift CNOT permutation, which is GF(2)-linear.)
__device__ __forceinline__ int sfx(int y) {
    y ^= y >> 1; y ^= y >> 2; y ^= y >> 4; y ^= y >> 8;
    return y;
}

struct C2 { float2 u00, u01, u10, u11; };

__device__ __forceinline__ C2 getU(int l, int q) {
    C2 c;
    c.u00 = g_Ug[l][q][0]; c.u01 = g_Ug[l][q][1];
    c.u10 = g_Ug[l][q][2]; c.u11 = g_Ug[l][q][3];
    return c;
}

// Complex 2x2 gate: x' = u00*x + u01*y ; y' = u10*x + u11*y
__device__ __forceinline__ void cgate(float2& x, float2& y, const C2& U) {
    float nxr = U.u00.x*x.x - U.u00.y*x.y + U.u01.x*y.x - U.u01.y*y.y;
    float nxi = U.u00.x*x.y + U.u00.y*x.x + U.u01.x*y.y + U.u01.y*y.x;
    float nyr = U.u10.x*x.x - U.u10.y*x.y + U.u11.x*y.x - U.u11.y*y.y;
    float nyi = U.u10.x*x.y + U.u10.y*x.x + U.u11.x*y.y + U.u11.y*y.x;
    x = make_float2(nxr, nxi);
    y = make_float2(nyr, nyi);
}

// Three gates on the s-bits of a[16] (a[2s],a[2s+1] = pair s): q0 on s-bit0,
// q1 on s-bit1, q2 on s-bit2.
__device__ __forceinline__ void gates3(float2 a[16], int l, int q0, int q1, int q2) {
    {
        C2 U = getU(l, q0);
#pragma unroll
        for (int s = 0; s < 8; s++) if (!(s & 1)) {
            cgate(a[2*s],   a[2*(s|1)],   U);
            cgate(a[2*s+1], a[2*(s|1)+1], U);
        }
    }
    {
        C2 U = getU(l, q1);
#pragma unroll
        for (int s = 0; s < 8; s++) if (!(s & 2)) {
            cgate(a[2*s],   a[2*(s|2)],   U);
            cgate(a[2*s+1], a[2*(s|2)+1], U);
        }
    }
    {
        C2 U = getU(l, q2);
#pragma unroll
        for (int s = 0; s < 8; s++) if (!(s & 4)) {
            cgate(a[2*s],   a[2*(s|4)],   U);
            cgate(a[2*s+1], a[2*(s|4)+1], U);
        }
    }
}

// Middle pass: LDS from sh, 3 gates, STS to sh.
__device__ __forceinline__ void mid_pass(float4* sh4, int t, int pb,
                                         int q0, int q1, int q2, int l) {
    const int low = t & ((1 << pb) - 1);
    const int hi  = t >> pb;
    const int qbase = (hi << (pb + 3)) | low;
    float2 a[16];
#pragma unroll
    for (int s = 0; s < 8; s++) {
        float4 v = sh4[sig(qbase | (s << pb))];
        a[2*s]   = make_float2(v.x, v.y);
        a[2*s+1] = make_float2(v.z, v.w);
    }
    gates3(a, l, q0, q1, q2);
#pragma unroll
    for (int s = 0; s < 8; s++) {
        sh4[sig(qbase | (s << pb))] =
            make_float4(a[2*s].x, a[2*s].y, a[2*s+1].x, a[2*s+1].y);
    }
}

// ---------------------------------------------------------------------------
// Norm reduction (reads inputs only)
// ---------------------------------------------------------------------------
__global__ void norm_part(const float* __restrict__ re, const float* __restrict__ im) {
    int tid = threadIdx.x;
    int base = blockIdx.x * 4096;
    float acc = 0.f;
#pragma unroll
    for (int k = 0; k < 16; k++) {
        int idx = base + k * 256 + tid;
        float r = re[idx], m = im[idx];
        acc = fmaf(r, r, acc);
        acc = fmaf(m, m, acc);
    }
    for (int off = 16; off; off >>= 1) acc += __shfl_xor_sync(0xffffffffu, acc, off);
    __shared__ float ws[8];
    int lane = tid & 31, wp = tid >> 5;
    if (lane == 0) ws[wp] = acc;
    __syncthreads();
    if (wp == 0) {
        float v = (lane < 8) ? ws[lane] : 0.f;
        for (int off = 4; off; off >>= 1) v += __shfl_xor_sync(0xffffffffu, v, off);
        if (lane == 0) g_norm_partial[blockIdx.x] = v;
    }
}

__global__ void norm_finalize() {
    int tid = threadIdx.x;
    float v = g_norm_partial[tid];
    for (int off = 16; off; off >>= 1) v += __shfl_xor_sync(0xffffffffu, v, off);
    __shared__ float ws[32];
    int lane = tid & 31, wp = tid >> 5;
    if (lane == 0) ws[wp] = v;
    __syncthreads();
    if (wp == 0) {
        float s = ws[lane];
        for (int off = 16; off; off >>= 1) s += __shfl_xor_sync(0xffffffffu, s, off);
        if (lane == 0) g_inv_norm = rsqrtf(s);
    }
}

// ---------------------------------------------------------------------------
// Fused single-qubit unitaries  U = RZ * RY * RX
// ---------------------------------------------------------------------------
__device__ __forceinline__ float2 cmulf(float2 a, float2 b) {
    return make_float2(a.x * b.x - a.y * b.y, a.x * b.y + a.y * b.x);
}

__global__ void make_gates(const float* __restrict__ params) {
    int t = threadIdx.x;
    if (t >= NL * NQ) return;
    int l = t / NQ, q = t % NQ;
    const float* p = params + (l * NQ + q) * 3;
    float tx = 0.5f * p[0], ty = 0.5f * p[1], tz = 0.5f * p[2];
    float cx = cosf(tx), sx = sinf(tx);
    float cy = cosf(ty), sy = sinf(ty);
    float cz = cosf(tz), sz = sinf(tz);
    float2 m00 = make_float2( cy * cx,  sy * sx);
    float2 m01 = make_float2(-sy * cx, -cy * sx);
    float2 m10 = make_float2( sy * cx, -cy * sx);
    float2 m11 = make_float2( cy * cx, -sy * sx);
    float2 e0 = make_float2(cz, -sz);
    float2 e1 = make_float2(cz,  sz);
    g_Ug[l][q][0] = cmulf(e0, m00);
    g_Ug[l][q][1] = cmulf(e0, m01);
    g_Ug[l][q][2] = cmulf(e1, m10);
    g_Ug[l][q][3] = cmulf(e1, m11);
}

// ---------------------------------------------------------------------------
// Kernel A: 4096-pair tile over global-pair bits {0..2} U {12..20}.
//   gp = ((q>>3)<<12) | (blk<<3) | (q&7);  tile q bit k (k>=3) -> qubit 11-k.
// Pass 1 (fused w/ global load, pb=3): gates 8,7,6.
// Pass 2 (smem, pb=6): gates 5,4,3.
// Pass 3 (fused w/ global store, pb=9): gates 2,1,0, then scatter with the
//   inverse CNOT permutation: dest = (p&7) | (sfx(p)&0xFF8)  [f(q)=q^((q>>1)&0x7F8)].
// ---------------------------------------------------------------------------
__global__ void __launch_bounds__(512, 2)
layerA_kernel(int layer, const float* __restrict__ sre, const float* __restrict__ sim, int first) {
    extern __shared__ float4 sh4[];
    const int t = threadIdx.x;
    const int blk = blockIdx.x;   // gp bits 3..11

    float2 a[16];

    // ---- pass 1: global -> regs, gates 8,7,6, STS ----
    {
        const int qb = ((t >> 3) << 6) | (t & 7);
        if (first) {
            float sc = g_inv_norm;
#pragma unroll
            for (int s = 0; s < 8; s++) {
                int q = qb | (s << 3);
                int gp = ((q >> 3) << 12) | (blk << 3) | (q & 7);
                float2 r2 = *(const float2*)&sre[gp << 1];
                float2 i2 = *(const float2*)&sim[gp << 1];
                a[2*s]   = make_float2(r2.x * sc, i2.x * sc);
                a[2*s+1] = make_float2(r2.y * sc, i2.y * sc);
            }
        } else {
#pragma unroll
            for (int s = 0; s < 8; s++) {
                int q = qb | (s << 3);
                int gp = ((q >> 3) << 12) | (blk << 3) | (q & 7);
                float4 v = g_state[gp];
                a[2*s]   = make_float2(v.x, v.y);
                a[2*s+1] = make_float2(v.z, v.w);
            }
        }
        gates3(a, layer, 8, 7, 6);
#pragma unroll
        for (int s = 0; s < 8; s++) {
            sh4[sig(qb | (s << 3))] =
                make_float4(a[2*s].x, a[2*s].y, a[2*s+1].x, a[2*s+1].y);
        }
    }
    __syncthreads();

    // ---- pass 2: smem, gates 5,4,3 ----
    mid_pass(sh4, t, 6, 5, 4, 3, layer);
    __syncthreads();

    // ---- pass 3: LDS, gates 2,1,0, scatter STG with inverse CNOT perm ----
    {
#pragma unroll
        for (int s = 0; s < 8; s++) {
            float4 v = sh4[sig(t | (s << 9))];
            a[2*s]   = make_float2(v.x, v.y);
            a[2*s+1] = make_float2(v.z, v.w);
        }
        gates3(a, layer, 2, 1, 0);
        const int dA = (t & 7) | (sfx(t) & 0xFF8);
#pragma unroll
        for (int s = 0; s < 8; s++) {
            int dest = dA ^ (sfx(s << 9) & 0xFF8);
            int gp = ((dest >> 3) << 12) | (blk << 3) | (dest & 7);
            g_state[gp] = make_float4(a[2*s].x, a[2*s].y, a[2*s+1].x, a[2*s+1].y);
        }
    }
}

// ---------------------------------------------------------------------------
// Kernel B: contiguous 4096-pair tile (pair base = blk<<12).
//   in-pair -> qubit 21; tile q bit k -> qubit 20-k.
// Pass 1 (fused load, pb=0): intra gate 21 + gates 20,19,18.
// Pass 2 (pb=3): 17,16,15.  Pass 3 (pb=6): 14,13,12.
// Pass 4 (fused store, pb=9): gates 11,10,9, scatter with inverse of
//   f(q)=q^((q>>1)&0x7FF)^((blk&1)<<11): dest = sfx(p) ^ (blk&1 ? 0xFFF : 0);
//   halves swapped iff dest odd.
// ---------------------------------------------------------------------------
__global__ void __launch_bounds__(512, 2)
layerB_kernel(int layer) {
    extern __shared__ float4 sh4[];
    const int t = threadIdx.x;
    const int blk = blockIdx.x;
    const int base = blk << 12;   // pair base

    float2 a[16];

    // ---- pass 1: global -> regs (contiguous), intra 21 + gates 20,19,18, STS ----
    {
        const int qb = t << 3;
#pragma unroll
        for (int s = 0; s < 8; s++) {
            float4 v = g_state[base + (qb | s)];
            a[2*s]   = make_float2(v.x, v.y);
            a[2*s+1] = make_float2(v.z, v.w);
        }
        {
            C2 U = getU(layer, 21);
#pragma unroll
            for (int s = 0; s < 8; s++) cgate(a[2*s], a[2*s+1], U);
        }
        gates3(a, layer, 20, 19, 18);
#pragma unroll
        for (int s = 0; s < 8; s++) {
            sh4[sig(qb | s)] =
                make_float4(a[2*s].x, a[2*s].y, a[2*s+1].x, a[2*s+1].y);
        }
    }
    __syncthreads();

    // ---- pass 2 & 3 ----
    mid_pass(sh4, t, 3, 17, 16, 15, layer);
    __syncthreads();
    mid_pass(sh4, t, 6, 14, 13, 12, layer);
    __syncthreads();

    // ---- pass 4: LDS, gates 11,10,9, scatter STG with inverse CNOT perm ----
    {
#pragma unroll
        for (int s = 0; s < 8; s++) {
            float4 v = sh4[sig(t | (s << 9))];
            a[2*s]   = make_float2(v.x, v.y);
            a[2*s+1] = make_float2(v.z, v.w);
        }
        gates3(a, layer, 11, 10, 9);
        const int dB = sfx(t);
        const int bm = (blk & 1) ? 0xFFF : 0;
#pragma unroll
        for (int s = 0; s < 8; s++) {
            int dest = dB ^ sfx(s << 9) ^ bm;
            float4 v = make_float4(a[2*s].x, a[2*s].y, a[2*s+1].x, a[2*s+1].y);
            if (dest & 1) v = make_float4(v.z, v.w, v.x, v.y);
            g_state[base + dest] = v;
        }
    }
}

// ---------------------------------------------------------------------------
// Z expectation values over pair layout. Amp bits: 0 = in-pair, 1..10 = tid,
// 11..13 = iter, 14..21 = blk.
// ---------------------------------------------------------------------------
__global__ void expval_kernel() {
    __shared__ float wsum[15][33];
    int tid = threadIdx.x, blk = blockIdx.x;
    int lane = tid & 31, wp = tid >> 5;
    float T = 0.f, D = 0.f, U0 = 0.f, U1 = 0.f, U2 = 0.f;
    int base = blk << 13;
#pragma unroll
    for (int i = 0; i < 8; i++) {
        float4 v = g_state[base + (i << 10) + tid];
        float p0 = fmaf(v.x, v.x, v.y * v.y);
        float p1 = fmaf(v.z, v.z, v.w * v.w);
        float p = p0 + p1;
        T += p;
        D += p0 - p1;
        if (i & 1) U0 += p;
        if (i & 2) U1 += p;
        if (i & 4) U2 += p;
    }
    float z[15];
    z[0] = D;
#pragma unroll
    for (int b = 0; b < 10; b++) z[b + 1] = ((tid >> b) & 1) ? -T : T;
    z[11] = T - 2.f * U0;
    z[12] = T - 2.f * U1;
    z[13] = T - 2.f * U2;
    z[14] = T;
#pragma unroll
    for (int b = 0; b < 15; b++) {
        float v = z[b];
        for (int off = 16; off; off >>= 1) v += __shfl_xor_sync(0xffffffffu, v, off);
        if (lane == 0) wsum[b][wp] = v;
    }
    __syncthreads();
    if (tid < 15) {
        float s = 0.f;
        for (int w = 0; w < 32; w++) s += wsum[tid][w];
        wsum[tid][32] = s;
    }
    __syncthreads();
    if (tid < 22) {
        float v;
        if (tid < 14) v = wsum[tid][32];
        else          v = (((blk >> (tid - 14)) & 1) ? -wsum[14][32] : wsum[14][32]);
        g_zpart[blk][tid] = v;
    }
}

__global__ void final_reduce(float* __restrict__ out) {
    int q = threadIdx.x;
    if (q >= 22) return;
    int b = 21 - q;   // qubit q <-> amp bit 21-q
    float s = 0.f;
    for (int i = 0; i < 256; i++) s += g_zpart[i][b];
    out[q] = s;
}

// ---------------------------------------------------------------------------
extern "C" void kernel_launch(void* const* d_in, const int* in_sizes, int n_in,
                              void* d_out, int out_size) {
    const float* params = (const float*)d_in[0];
    const float* re     = (const float*)d_in[1];
    const float* im     = (const float*)d_in[2];
    float* out = (float*)d_out;

    cudaFuncSetAttribute(layerA_kernel, cudaFuncAttributeMaxDynamicSharedMemorySize, 65536);
    cudaFuncSetAttribute(layerB_kernel, cudaFuncAttributeMaxDynamicSharedMemorySize, 65536);

    norm_part<<<1024, 256>>>(re, im);
    norm_finalize<<<1, 1024>>>();
    make_gates<<<1, 128>>>(params);
    for (int l = 0; l < NL; l++) {
        layerA_kernel<<<512, 512, 65536>>>(l, re, im, l == 0 ? 1 : 0);
        layerB_kernel<<<512, 512, 65536>>>(l);
    }
    expval_kernel<<<256, 1024>>>();
    final_reduce<<<1, 32>>>(out);
}